// round 4
// baseline (speedup 1.0000x reference)
#include <cuda_runtime.h>

// DendriticLayer: B=512, N_IN=1024, N_OUT=256, T=100, dt=1.
// CONN block-diagonal (4 inputs per output) -> per-(b,o) scalar recurrence.
// u_t = (0.9/d) u_{t-1} + 0.1 * sum_j c_j * ind_j(t);  exp(2 v_t) = exp2(u_t * E_t)
// E_t = 2*log2(e)*d^t is a compile-time immediate per unrolled step.
// ind_j(t) = saturate(t + 1 - ceil(s_j))  (exact for integer t)
// R4: 2 independent elements per thread (ILP) to fill MUFU/FFMA latency gaps.

#define NSTEPS 100

__device__ __forceinline__ float ex2(float x) {
    float y;
    asm("ex2.approx.ftz.f32 %0, %1;" : "=f"(y) : "f"(x));
    return y;
}

__host__ __device__ constexpr double cpow(double b, int n) {
    return n == 0 ? 1.0 : b * cpow(b, n - 1);
}

constexpr double D1 = 0.81873075307798185867;   // exp(-0.2)
constexpr double RD = 0.9 / D1;                 // (1-a)/d
constexpr double K2 = 2.8853900817779268147;    // 2*log2(e)

struct Elem {
    float q0, q1, q2, q3;   // 1 - ceil(s_j)
    float c0, c1, c2, c3;   // 0.1 * w_j * exp(s_j/5)
    float u, S, WS;
};

__device__ __forceinline__ void init_elem(Elem& e, const float4 s4, const float4 w4) {
    e.q0 = 1.0f - ceilf(s4.x);
    e.q1 = 1.0f - ceilf(s4.y);
    e.q2 = 1.0f - ceilf(s4.z);
    e.q3 = 1.0f - ceilf(s4.w);
    e.c0 = 0.1f * w4.x * __expf(0.2f * s4.x);
    e.c1 = 0.1f * w4.y * __expf(0.2f * s4.y);
    e.c2 = 0.1f * w4.z * __expf(0.2f * s4.z);
    e.c3 = 0.1f * w4.w * __expf(0.2f * s4.w);
    e.u = 0.0f; e.S = 0.0f; e.WS = 0.0f;
}

template <int T>
__device__ __forceinline__ void step_one(Elem& st) {
    constexpr float tf  = (float)T;
    constexpr float Et  = (float)(K2 * cpow(D1, T));
    constexpr float rdf = (float)RD;

    const float i0 = __saturatef(tf + st.q0);
    const float i1 = __saturatef(tf + st.q1);
    const float i2 = __saturatef(tf + st.q2);
    const float i3 = __saturatef(tf + st.q3);

    float Cp = i0 * st.c0;
    Cp = fmaf(i1, st.c1, Cp);
    Cp = fmaf(i2, st.c2, Cp);
    Cp = fmaf(i3, st.c3, Cp);

    st.u = fmaf(st.u, rdf, Cp);
    const float e = ex2(st.u * Et);
    st.S += e;
    st.WS = fmaf(e, tf, st.WS);
}

template <int T>
__device__ __forceinline__ void steps(Elem& a, Elem& b) {
    if constexpr (T < NSTEPS) {
        step_one<T>(a);      // two independent chains interleave in the
        step_one<T>(b);      // scheduler: B's work fills A's MUFU shadow
        steps<T + 1>(a, b);
    }
}

__global__ __launch_bounds__(64)
void dendritic_kernel(const float* __restrict__ spikes,  // [512,1024]
                      const float* __restrict__ W,       // [256,1024]
                      float* __restrict__ out)           // [512,256]
{
    const int idx  = blockIdx.x * blockDim.x + threadIdx.x;   // elem A: b*256+o, b in [0,256)
    const int idx2 = idx + 65536;                             // elem B: same o, b+256
    const int o    = idx & 255;

    // spikes[b*1024 + 4o..4o+3] -> float4 index = idx (coalesced)
    const float4 sA = reinterpret_cast<const float4*>(spikes)[idx];
    const float4 sB = reinterpret_cast<const float4*>(spikes)[idx2];
    // W[o*1024 + 4o..4o+3] -> float4 index 257*o (L1-resident, shared by both elems)
    const float4 w4 = reinterpret_cast<const float4*>(W)[257 * o];

    Elem a, b;
    init_elem(a, sA, w4);
    init_elem(b, sB, w4);

    steps<0>(a, b);

    out[idx]  = a.WS / a.S;
    out[idx2] = b.WS / b.S;
}

extern "C" void kernel_launch(void* const* d_in, const int* in_sizes, int n_in,
                              void* d_out, int out_size)
{
    const float* spikes = (const float*)d_in[0];  // [512*1024]
    const float* W      = (const float*)d_in[1];  // [256*1024]
    float* out          = (float*)d_out;          // [512*256]

    // 65536 threads, 2 elems each; 1024 blocks of 64 -> 6.92 blocks/SM (balanced)
    dendritic_kernel<<<1024, 64>>>(spikes, W, out);
}

// round 5
// speedup vs baseline: 1.0025x; 1.0025x over previous
#include <cuda_runtime.h>

// DendriticLayer: B=512, N_IN=1024, N_OUT=256, T=100, dt=1.
// CONN block-diagonal (4 inputs per output) -> per-(b,o) scalar recurrence.
// u_t = (0.9/d) u_{t-1} + sum_j c_j [t >= ceil(s_j)]   (c_j absorbs the 0.1)
// exp(2 v_t) = exp2(u_t * E_t),  E_t = 2*log2(e)*d^t  (compile-time immediate)
// out = (sum_t t*e_t)/(sum_t e_t)  (softmax w/o max-sub: arg in [0,~17])
//
// R5: indicators as compare+select (FSETP+FSEL -> ALU pipe) instead of
// FADD.SAT+FFMA (fma pipe). R3 was fma-pipe throughput bound with alu idle;
// this splits the per-step work ~13 fma-cyc / ~16 alu-cyc across both pipes.

#define NSTEPS 100

__device__ __forceinline__ float ex2(float x) {
    float y;
    asm("ex2.approx.ftz.f32 %0, %1;" : "=f"(y) : "f"(x));
    return y;
}

__host__ __device__ constexpr double cpow(double b, int n) {
    return n == 0 ? 1.0 : b * cpow(b, n - 1);
}

constexpr double D1 = 0.81873075307798185867;   // exp(-0.2)
constexpr double RD = 0.9 / D1;                 // (1-a)/d
constexpr double K2 = 2.8853900817779268147;    // 2*log2(e)

struct St {
    float e0, e1, e2, e3;   // ceil(s_j): activation threshold (t >= e_j)
    float c0, c1, c2, c3;   // 0.1 * w_j * exp(s_j/5)
    float u, S, WS;
};

template <int T>
__device__ __forceinline__ void steps(St& st) {
    if constexpr (T < NSTEPS) {
        constexpr float tf  = (float)T;
        constexpr float Et  = (float)(K2 * cpow(D1, T));
        constexpr float rdf = (float)RD;

        // FSETP + FSEL  (alu pipe; fma pipe stays free)
        const float v0 = (tf >= st.e0) ? st.c0 : 0.0f;
        const float v1 = (tf >= st.e1) ? st.c1 : 0.0f;
        const float v2 = (tf >= st.e2) ? st.c2 : 0.0f;
        const float v3 = (tf >= st.e3) ? st.c3 : 0.0f;

        const float Cp = (v0 + v1) + (v2 + v3);   // 3 FADD (fma pipe)

        st.u = fmaf(st.u, rdf, Cp);               // FFMA
        const float e = ex2(st.u * Et);           // FMUL-imm + MUFU.EX2
        st.S += e;                                // FADD
        st.WS = fmaf(e, tf, st.WS);               // FFMA-imm (rt 1)

        steps<T + 1>(st);
    }
}

__global__ __launch_bounds__(128)
void dendritic_kernel(const float* __restrict__ spikes,  // [512,1024]
                      const float* __restrict__ W,       // [256,1024]
                      float* __restrict__ out)           // [512,256]
{
    const int idx = blockIdx.x * blockDim.x + threadIdx.x;  // b*256 + o
    const int o   = idx & 255;

    // spikes[b*1024 + 4o..4o+3] -> float4 index = idx (coalesced)
    const float4 s4 = reinterpret_cast<const float4*>(spikes)[idx];
    // W[o*1024 + 4o..4o+3] -> float4 index 257*o (L1-resident)
    const float4 w4 = reinterpret_cast<const float4*>(W)[257 * o];

    St st;
    st.e0 = ceilf(s4.x);
    st.e1 = ceilf(s4.y);
    st.e2 = ceilf(s4.z);
    st.e3 = ceilf(s4.w);
    st.c0 = 0.1f * w4.x * __expf(0.2f * s4.x);
    st.c1 = 0.1f * w4.y * __expf(0.2f * s4.y);
    st.c2 = 0.1f * w4.z * __expf(0.2f * s4.z);
    st.c3 = 0.1f * w4.w * __expf(0.2f * s4.w);
    st.u = 0.0f;
    st.S = 0.0f;
    st.WS = 0.0f;

    steps<0>(st);

    out[idx] = st.WS / st.S;
}

extern "C" void kernel_launch(void* const* d_in, const int* in_sizes, int n_in,
                              void* d_out, int out_size)
{
    const float* spikes = (const float*)d_in[0];  // [512*1024]
    const float* W      = (const float*)d_in[1];  // [256*1024]
    float* out          = (float*)d_out;          // [512*256]

    dendritic_kernel<<<1024, 128>>>(spikes, W, out);
}